// round 1
// baseline (speedup 1.0000x reference)
#include <cuda_runtime.h>
#include <cuda_bf16.h>
#include <cstdint>
#include <cstdio>

// Problem constants
#define Bn 8
#define Qn 900
#define EMBED 256
#define HEADS 8
#define LEVELS 4
#define POINTS 4
#define HEAD_DIM 32
#define NUM_KEYS 13294
#define BQ (Bn*Qn)            // 7200
#define MV (Bn*NUM_KEYS)      // 106352

// Scratch (device globals; no runtime allocation)
__device__ float g_v  [(size_t)MV * EMBED];   // projected value [B,K,256]
__device__ float g_off[(size_t)BQ * 256];     // offset projections
__device__ float g_aw [(size_t)BQ * 128];     // attention logits
__device__ float g_tmp[(size_t)BQ * 256];     // msda output before W_out

// ---------------------------------------------------------------------------
// Tiled fp32 GEMM with bias: C[M,N] = A[M,K] * B[K,N] + bias[N]
// BM=BN=64, BK=16, 256 threads, 4x4 register tile per thread.
// N must be a multiple of 64; K a multiple of 16; M arbitrary (guarded).
// ---------------------------------------------------------------------------
__global__ __launch_bounds__(256) void gemm_bias(
    const float* __restrict__ A, const float* __restrict__ Bm,
    const float* __restrict__ bias, float* __restrict__ C,
    int M, int N, int Kd)
{
    const int BM = 64, BN = 64, BK = 16;
    __shared__ float As[BK][BM + 4];   // [k][m], padded
    __shared__ float Bs[BK][BN];       // [k][n]

    int tid = threadIdx.x;
    int brow = blockIdx.y * BM;
    int bcol = blockIdx.x * BN;
    int ty = tid / 16;   // 0..15 -> row group
    int tx = tid % 16;   // 0..15 -> col group

    float acc[4][4] = {};

    for (int k0 = 0; k0 < Kd; k0 += BK) {
        // Load A tile (64x16) as float4: 256 float4 = 256 threads
        {
            int r  = tid >> 2;          // 0..63
            int c4 = tid & 3;           // 0..3
            int gr = brow + r;
            float4 av = make_float4(0.f, 0.f, 0.f, 0.f);
            if (gr < M)
                av = *reinterpret_cast<const float4*>(A + (size_t)gr * Kd + k0 + c4 * 4);
            As[c4*4 + 0][r] = av.x;
            As[c4*4 + 1][r] = av.y;
            As[c4*4 + 2][r] = av.z;
            As[c4*4 + 3][r] = av.w;
        }
        // Load B tile (16x64) as float4
        {
            int r  = tid >> 4;          // 0..15
            int c4 = tid & 15;          // 0..15
            float4 bv = *reinterpret_cast<const float4*>(Bm + (size_t)(k0 + r) * N + bcol + c4 * 4);
            *reinterpret_cast<float4*>(&Bs[r][c4 * 4]) = bv;
        }
        __syncthreads();

        #pragma unroll
        for (int kk = 0; kk < BK; kk++) {
            float4 a4 = *reinterpret_cast<const float4*>(&As[kk][ty * 4]);
            float4 b4 = *reinterpret_cast<const float4*>(&Bs[kk][tx * 4]);
            float a[4] = {a4.x, a4.y, a4.z, a4.w};
            float b[4] = {b4.x, b4.y, b4.z, b4.w};
            #pragma unroll
            for (int i = 0; i < 4; i++)
                #pragma unroll
                for (int j = 0; j < 4; j++)
                    acc[i][j] += a[i] * b[j];
        }
        __syncthreads();
    }

    #pragma unroll
    for (int i = 0; i < 4; i++) {
        int gr = brow + ty * 4 + i;
        if (gr >= M) continue;
        #pragma unroll
        for (int j = 0; j < 4; j++) {
            int gc = bcol + tx * 4 + j;
            C[(size_t)gr * N + gc] = acc[i][j] + bias[gc];
        }
    }
}

// ---------------------------------------------------------------------------
// Fused: softmax over attn logits, sampling-location compute, bilinear
// sampling + weighted aggregation. One block per (b,q), 256 threads.
// Warp w = head w, lane = channel within head. Output: g_tmp[bq][h*32+d].
// ---------------------------------------------------------------------------
__global__ __launch_bounds__(256) void msda_sample(
    const float* __restrict__ ref,          // [B,Q,L,2]
    const float* __restrict__ offp,         // [BQ,256]
    const float* __restrict__ awp,          // [BQ,128]
    const int*   __restrict__ shapes,       // [L,2] (H,W)
    const int*   __restrict__ starts,       // [L]
    const float* __restrict__ v,            // [B,K,256]
    float*       __restrict__ tmp)          // [BQ,256]
{
    int bq = blockIdx.x;
    int b  = bq / Qn;
    int tid = threadIdx.x;

    __shared__ float offs[256];
    __shared__ float aws[128];
    __shared__ float sx[128], sy[128], swt[128];
    __shared__ int shH[LEVELS], shW[LEVELS], sst[LEVELS];

    offs[tid] = offp[(size_t)bq * 256 + tid];
    if (tid < 128) aws[tid] = awp[(size_t)bq * 128 + tid];
    if (tid < LEVELS) {
        shH[tid] = shapes[tid * 2 + 0];
        shW[tid] = shapes[tid * 2 + 1];
        sst[tid] = starts[tid];
    }
    __syncthreads();

    // softmax over 16 (L*P) per head
    if (tid < HEADS) {
        int base = tid * 16;
        float m = -1e30f;
        #pragma unroll
        for (int i = 0; i < 16; i++) m = fmaxf(m, aws[base + i]);
        float s = 0.f;
        #pragma unroll
        for (int i = 0; i < 16; i++) { float e = __expf(aws[base + i] - m); aws[base + i] = e; s += e; }
        float inv = 1.f / s;
        #pragma unroll
        for (int i = 0; i < 16; i++) aws[base + i] *= inv;
    }
    __syncthreads();

    // sampling positions in pixel coords (x = ref_x*W + off_x - 0.5)
    if (tid < 128) {
        int s = tid;                  // s = h*16 + l*4 + p
        int l = (s >> 2) & 3;
        float Wl = (float)shW[l], Hl = (float)shH[l];
        float rx = ref[(size_t)bq * (LEVELS * 2) + l * 2 + 0];
        float ry = ref[(size_t)bq * (LEVELS * 2) + l * 2 + 1];
        sx[s] = rx * Wl + offs[2 * s + 0] - 0.5f;
        sy[s] = ry * Hl + offs[2 * s + 1] - 0.5f;
        swt[s] = aws[s];
    }
    __syncthreads();

    int h = tid >> 5;       // warp = head
    int lane = tid & 31;    // lane = channel
    float acc = 0.f;
    const float* vb = v + (size_t)b * NUM_KEYS * EMBED + h * HEAD_DIM + lane;

    #pragma unroll
    for (int i = 0; i < 16; i++) {
        int s = h * 16 + i;
        int l = i >> 2;
        int Hl = shH[l], Wl = shW[l], st = sst[l];
        float x = sx[s], y = sy[s];
        float wgt = swt[s];
        float x0f = floorf(x), y0f = floorf(y);
        int x0 = (int)x0f, y0 = (int)y0f;
        float fx = x - x0f, fy = y - y0f;
        int x1 = x0 + 1, y1 = y0 + 1;
        bool bx0 = (x0 >= 0) & (x0 < Wl);
        bool bx1 = (x1 >= 0) & (x1 < Wl);
        bool by0 = (y0 >= 0) & (y0 < Hl);
        bool by1 = (y1 >= 0) & (y1 < Hl);
        int cx0 = min(max(x0, 0), Wl - 1), cx1 = min(max(x1, 0), Wl - 1);
        int cy0 = min(max(y0, 0), Hl - 1), cy1 = min(max(y1, 0), Hl - 1);
        float v00 = (bx0 && by0) ? vb[(size_t)(st + cy0 * Wl + cx0) * EMBED] : 0.f;
        float v01 = (bx1 && by0) ? vb[(size_t)(st + cy0 * Wl + cx1) * EMBED] : 0.f;
        float v10 = (bx0 && by1) ? vb[(size_t)(st + cy1 * Wl + cx0) * EMBED] : 0.f;
        float v11 = (bx1 && by1) ? vb[(size_t)(st + cy1 * Wl + cx1) * EMBED] : 0.f;
        float w00 = (1.f - fx) * (1.f - fy);
        float w01 = fx * (1.f - fy);
        float w10 = (1.f - fx) * fy;
        float w11 = fx * fy;
        acc += wgt * (v00 * w00 + v01 * w01 + v10 * w10 + v11 * w11);
    }

    tmp[(size_t)bq * 256 + tid] = acc;
}

// ---------------------------------------------------------------------------
extern "C" void kernel_launch(void* const* d_in, const int* in_sizes, int n_in,
                              void* d_out, int out_size)
{
    const float* query  = (const float*)d_in[0];
    const float* refpts = (const float*)d_in[1];
    const float* value  = (const float*)d_in[2];
    const int*   shapes = (const int*)  d_in[3];
    const int*   starts = (const int*)  d_in[4];
    const float* W_off  = (const float*)d_in[5];
    const float* b_off  = (const float*)d_in[6];
    const float* W_attn = (const float*)d_in[7];
    const float* b_attn = (const float*)d_in[8];
    const float* W_val  = (const float*)d_in[9];
    const float* b_val  = (const float*)d_in[10];
    const float* W_out  = (const float*)d_in[11];
    const float* b_out  = (const float*)d_in[12];
    float* out = (float*)d_out;

    float *pv, *poff, *paw, *ptmp;
    cudaGetSymbolAddress((void**)&pv,   g_v);
    cudaGetSymbolAddress((void**)&poff, g_off);
    cudaGetSymbolAddress((void**)&paw,  g_aw);
    cudaGetSymbolAddress((void**)&ptmp, g_tmp);

    // 1) value projection: [106352,256] @ [256,256] + b_val -> g_v
    {
        dim3 grid(EMBED / 64, (MV + 63) / 64);
        gemm_bias<<<grid, 256>>>(value, W_val, b_val, pv, MV, EMBED, EMBED);
    }
    // 2a) offset projection: [7200,256] @ [256,256] + b_off -> g_off
    {
        dim3 grid(256 / 64, (BQ + 63) / 64);
        gemm_bias<<<grid, 256>>>(query, W_off, b_off, poff, BQ, 256, EMBED);
    }
    // 2b) attn projection: [7200,256] @ [256,128] + b_attn -> g_aw
    {
        dim3 grid(128 / 64, (BQ + 63) / 64);
        gemm_bias<<<grid, 256>>>(query, W_attn, b_attn, paw, BQ, 128, EMBED);
    }
    // 3) fused softmax + sampling
    msda_sample<<<BQ, 256>>>(refpts, poff, paw, shapes, starts, pv, ptmp);
    // 4) output projection: [7200,256] @ [256,256] + b_out -> out
    {
        dim3 grid(256 / 64, (BQ + 63) / 64);
        gemm_bias<<<grid, 256>>>(ptmp, W_out, b_out, out, BQ, 256, EMBED);
    }
}

// round 2
// speedup vs baseline: 1.9630x; 1.9630x over previous
#include <cuda_runtime.h>
#include <cuda_bf16.h>
#include <cstdint>

// Problem constants
#define Bn 8
#define Qn 900
#define EMBED 256
#define HEADS 8
#define LEVELS 4
#define POINTS 4
#define HEAD_DIM 32
#define NUM_KEYS 13294
#define BQ (Bn*Qn)            // 7200
#define MV (Bn*NUM_KEYS)      // 106352

// Scratch (device globals; no runtime allocation)
__device__ float g_v  [(size_t)MV * EMBED];
__device__ float g_off[(size_t)BQ * 256];
__device__ float g_aw [(size_t)BQ * 128];
__device__ float g_tmp[(size_t)BQ * 256];

__device__ __forceinline__ uint32_t f2tf(float x) {
    uint32_t r; asm("cvt.rna.tf32.f32 %0, %1;" : "=r"(r) : "f"(x)); return r;
}

// ---------------------------------------------------------------------------
// TF32 tensor-core GEMM with bias: C[M,N] = A[M,K] * B[K,N] + bias[N]
// BM=128, BN=64, BK=32. 256 threads = 8 warps, warp tile 32x32.
// mma.sync.aligned.m16n8k8 tf32. N % 64 == 0, K % 32 == 0, M arbitrary.
// Smem strides 136/72: fragment-load banks = (8k + m) mod 32 -> conflict-free.
// ---------------------------------------------------------------------------
__global__ __launch_bounds__(256, 3) void gemm_tf32(
    const float* __restrict__ A, const float* __restrict__ B,
    const float* __restrict__ bias, float* __restrict__ C,
    int M, int N, int K)
{
    __shared__ uint32_t As[32][136];   // [k][m]
    __shared__ uint32_t Bs[32][72];    // [k][n]

    const int tid  = threadIdx.x;
    const int lane = tid & 31;
    const int w    = tid >> 5;
    const int gid  = lane >> 2;   // group (0..7)
    const int tig  = lane & 3;    // thread-in-group
    const int brow = blockIdx.y * 128;
    const int bcol = blockIdx.x * 64;
    const int m0   = (w >> 1) * 32;   // warp row offset
    const int n0   = (w & 1) * 32;    // warp col offset

    float acc[2][4][4];
    #pragma unroll
    for (int mi = 0; mi < 2; mi++)
        #pragma unroll
        for (int nj = 0; nj < 4; nj++)
            #pragma unroll
            for (int r = 0; r < 4; r++) acc[mi][nj][r] = 0.f;

    // A-tile loader mapping: 128 rows x 8 float4 per row; thread -> (row, 2 f4-slots, 4 f4 each)
    const int arow = tid >> 1;          // 0..127
    const int af0  = (tid & 1) * 4;     // f4 slot base 0 or 4

    float4 pa[4], pb[2];

    auto loadA = [&](int k0) {
        const float* Ar = A + (size_t)(brow + arow) * K + k0;
        bool ok = (brow + arow) < M;
        #pragma unroll
        for (int i = 0; i < 4; i++)
            pa[i] = ok ? *reinterpret_cast<const float4*>(Ar + (af0 + i) * 4)
                       : make_float4(0.f, 0.f, 0.f, 0.f);
    };
    auto storeA = [&]() {
        #pragma unroll
        for (int i = 0; i < 4; i++) {
            int kc = (af0 + i) * 4;
            As[kc + 0][arow] = f2tf(pa[i].x);
            As[kc + 1][arow] = f2tf(pa[i].y);
            As[kc + 2][arow] = f2tf(pa[i].z);
            As[kc + 3][arow] = f2tf(pa[i].w);
        }
    };
    auto loadB = [&](int k0) {
        #pragma unroll
        for (int i = 0; i < 2; i++) {
            int g = tid + 256 * i;
            int kr = g >> 4, c4 = g & 15;
            pb[i] = *reinterpret_cast<const float4*>(B + (size_t)(k0 + kr) * N + bcol + c4 * 4);
        }
    };
    auto storeB = [&]() {
        #pragma unroll
        for (int i = 0; i < 2; i++) {
            int g = tid + 256 * i;
            int kr = g >> 4, c4 = g & 15;
            Bs[kr][c4 * 4 + 0] = f2tf(pb[i].x);
            Bs[kr][c4 * 4 + 1] = f2tf(pb[i].y);
            Bs[kr][c4 * 4 + 2] = f2tf(pb[i].z);
            Bs[kr][c4 * 4 + 3] = f2tf(pb[i].w);
        }
    };
    auto compute = [&]() {
        #pragma unroll
        for (int ks = 0; ks < 4; ks++) {
            const int k = ks * 8;
            uint32_t a[2][4], b[4][2];
            #pragma unroll
            for (int mi = 0; mi < 2; mi++) {
                int mb = m0 + mi * 16 + gid;
                a[mi][0] = As[k + tig    ][mb    ];
                a[mi][1] = As[k + tig    ][mb + 8];
                a[mi][2] = As[k + tig + 4][mb    ];
                a[mi][3] = As[k + tig + 4][mb + 8];
            }
            #pragma unroll
            for (int nj = 0; nj < 4; nj++) {
                int nb = n0 + nj * 8 + gid;
                b[nj][0] = Bs[k + tig    ][nb];
                b[nj][1] = Bs[k + tig + 4][nb];
            }
            #pragma unroll
            for (int mi = 0; mi < 2; mi++)
                #pragma unroll
                for (int nj = 0; nj < 4; nj++) {
                    asm volatile(
                        "mma.sync.aligned.m16n8k8.row.col.f32.tf32.tf32.f32 "
                        "{%0,%1,%2,%3}, {%4,%5,%6,%7}, {%8,%9}, {%0,%1,%2,%3};"
                        : "+f"(acc[mi][nj][0]), "+f"(acc[mi][nj][1]),
                          "+f"(acc[mi][nj][2]), "+f"(acc[mi][nj][3])
                        : "r"(a[mi][0]), "r"(a[mi][1]), "r"(a[mi][2]), "r"(a[mi][3]),
                          "r"(b[nj][0]), "r"(b[nj][1]));
                }
        }
    };

    const int T = K / 32;
    loadA(0); loadB(0);
    storeA(); storeB();
    __syncthreads();
    for (int t = 0; t < T; t++) {
        if (t + 1 < T) { loadA((t + 1) * 32); loadB((t + 1) * 32); }
        compute();
        __syncthreads();
        if (t + 1 < T) { storeA(); storeB(); __syncthreads(); }
    }

    // Epilogue: c0/c1 -> (row, 2*tig, 2*tig+1); c2/c3 -> row+8
    #pragma unroll
    for (int mi = 0; mi < 2; mi++) {
        #pragma unroll
        for (int nj = 0; nj < 4; nj++) {
            int col = bcol + n0 + nj * 8 + 2 * tig;
            float b0 = bias[col], b1 = bias[col + 1];
            int r0 = brow + m0 + mi * 16 + gid;
            if (r0 < M) {
                float2 v0 = make_float2(acc[mi][nj][0] + b0, acc[mi][nj][1] + b1);
                *reinterpret_cast<float2*>(C + (size_t)r0 * N + col) = v0;
            }
            int r1 = r0 + 8;
            if (r1 < M) {
                float2 v1 = make_float2(acc[mi][nj][2] + b0, acc[mi][nj][3] + b1);
                *reinterpret_cast<float2*>(C + (size_t)r1 * N + col) = v1;
            }
        }
    }
}

// ---------------------------------------------------------------------------
// Fused softmax + sampling. One block per (b,q), 256 threads.
// Stage 1 (128 thr): softmax via 16-lane shuffles, compute per-sample corner
//   indices + attn-premultiplied bilinear weights -> smem.
// Stage 2 (256 thr): warp = head, lane = channel; 16 samples x 4 coalesced
//   128B gathers, fma with precomputed weights.
// ---------------------------------------------------------------------------
__global__ __launch_bounds__(256) void msda_sample(
    const float* __restrict__ ref,          // [B,Q,L,2]
    const float* __restrict__ offp,         // [BQ,256]
    const float* __restrict__ awp,          // [BQ,128]
    const int*   __restrict__ shapes,       // [L,2] (H,W)
    const int*   __restrict__ starts,       // [L]
    const float* __restrict__ v,            // [B,K,256]
    float*       __restrict__ tmp)          // [BQ,256]
{
    const int bq  = blockIdx.x;
    const int b   = bq / Qn;
    const int tid = threadIdx.x;

    __shared__ int4   sIdx[128];
    __shared__ float4 sW[128];

    if (tid < 128) {
        const int l = (tid >> 2) & 3;           // sample s = h*16 + l*4 + p
        const int Hl = shapes[2 * l], Wl = shapes[2 * l + 1];
        const int st = starts[l];

        // softmax across the 16 samples of this head (16-lane subgroup)
        float logit = awp[(size_t)bq * 128 + tid];
        float m = logit;
        #pragma unroll
        for (int d = 8; d >= 1; d >>= 1)
            m = fmaxf(m, __shfl_xor_sync(0xffffffffu, m, d));
        float e = __expf(logit - m);
        float s = e;
        #pragma unroll
        for (int d = 8; d >= 1; d >>= 1)
            s += __shfl_xor_sync(0xffffffffu, s, d);
        const float wgt = e / s;

        const float2 off = reinterpret_cast<const float2*>(offp)[(size_t)bq * 128 + tid];
        const float rx = ref[(size_t)bq * (LEVELS * 2) + 2 * l];
        const float ry = ref[(size_t)bq * (LEVELS * 2) + 2 * l + 1];
        const float x = rx * (float)Wl + off.x - 0.5f;
        const float y = ry * (float)Hl + off.y - 0.5f;

        const float x0f = floorf(x), y0f = floorf(y);
        const int x0 = (int)x0f, y0 = (int)y0f;
        const float fx = x - x0f, fy = y - y0f;
        const int x1 = x0 + 1, y1 = y0 + 1;
        const bool bx0 = (x0 >= 0) & (x0 < Wl);
        const bool bx1 = (x1 >= 0) & (x1 < Wl);
        const bool by0 = (y0 >= 0) & (y0 < Hl);
        const bool by1 = (y1 >= 0) & (y1 < Hl);
        const int cx0 = min(max(x0, 0), Wl - 1), cx1 = min(max(x1, 0), Wl - 1);
        const int cy0 = min(max(y0, 0), Hl - 1), cy1 = min(max(y1, 0), Hl - 1);

        sIdx[tid] = make_int4(st + cy0 * Wl + cx0, st + cy0 * Wl + cx1,
                              st + cy1 * Wl + cx0, st + cy1 * Wl + cx1);
        sW[tid] = make_float4(
            (bx0 && by0) ? (1.f - fx) * (1.f - fy) * wgt : 0.f,
            (bx1 && by0) ? fx * (1.f - fy) * wgt : 0.f,
            (bx0 && by1) ? (1.f - fx) * fy * wgt : 0.f,
            (bx1 && by1) ? fx * fy * wgt : 0.f);
    }
    __syncthreads();

    const int h    = tid >> 5;
    const int lane = tid & 31;
    const float* vb = v + (size_t)b * NUM_KEYS * EMBED + h * HEAD_DIM + lane;

    float acc = 0.f;
    #pragma unroll
    for (int i = 0; i < 16; i++) {
        const int4   id = sIdx[h * 16 + i];
        const float4 wv = sW[h * 16 + i];
        acc = fmaf(wv.x, vb[(size_t)id.x * EMBED], acc);
        acc = fmaf(wv.y, vb[(size_t)id.y * EMBED], acc);
        acc = fmaf(wv.z, vb[(size_t)id.z * EMBED], acc);
        acc = fmaf(wv.w, vb[(size_t)id.w * EMBED], acc);
    }
    tmp[(size_t)bq * 256 + tid] = acc;
}

// ---------------------------------------------------------------------------
extern "C" void kernel_launch(void* const* d_in, const int* in_sizes, int n_in,
                              void* d_out, int out_size)
{
    const float* query  = (const float*)d_in[0];
    const float* refpts = (const float*)d_in[1];
    const float* value  = (const float*)d_in[2];
    const int*   shapes = (const int*)  d_in[3];
    const int*   starts = (const int*)  d_in[4];
    const float* W_off  = (const float*)d_in[5];
    const float* b_off  = (const float*)d_in[6];
    const float* W_attn = (const float*)d_in[7];
    const float* b_attn = (const float*)d_in[8];
    const float* W_val  = (const float*)d_in[9];
    const float* b_val  = (const float*)d_in[10];
    const float* W_out  = (const float*)d_in[11];
    const float* b_out  = (const float*)d_in[12];
    float* out = (float*)d_out;

    float *pv, *poff, *paw, *ptmp;
    cudaGetSymbolAddress((void**)&pv,   g_v);
    cudaGetSymbolAddress((void**)&poff, g_off);
    cudaGetSymbolAddress((void**)&paw,  g_aw);
    cudaGetSymbolAddress((void**)&ptmp, g_tmp);

    // 1) value projection: [106352,256] @ [256,256]
    {
        dim3 grid(EMBED / 64, (MV + 127) / 128);
        gemm_tf32<<<grid, 256>>>(value, W_val, b_val, pv, MV, EMBED, EMBED);
    }
    // 2a) offset projection: [7200,256] @ [256,256]
    {
        dim3 grid(256 / 64, (BQ + 127) / 128);
        gemm_tf32<<<grid, 256>>>(query, W_off, b_off, poff, BQ, 256, EMBED);
    }
    // 2b) attn projection: [7200,256] @ [256,128]
    {
        dim3 grid(128 / 64, (BQ + 127) / 128);
        gemm_tf32<<<grid, 256>>>(query, W_attn, b_attn, paw, BQ, 128, EMBED);
    }
    // 3) fused softmax + sampling
    msda_sample<<<BQ, 256>>>(refpts, poff, paw, shapes, starts, pv, ptmp);
    // 4) output projection: [7200,256] @ [256,256]
    {
        dim3 grid(256 / 64, (BQ + 127) / 128);
        gemm_tf32<<<grid, 256>>>(ptmp, W_out, b_out, out, BQ, 256, EMBED);
    }
}

// round 5
// speedup vs baseline: 2.2566x; 1.1495x over previous
#include <cuda_runtime.h>
#include <cuda_bf16.h>
#include <cstdint>

// Problem constants
#define Bn 8
#define Qn 900
#define EMBED 256
#define HEADS 8
#define LEVELS 4
#define POINTS 4
#define HEAD_DIM 32
#define NUM_KEYS 13294
#define BQ (Bn*Qn)            // 7200
#define MV (Bn*NUM_KEYS)      // 106352

// Scratch (device globals; no runtime allocation)
__device__ float g_v  [(size_t)MV * EMBED];
__device__ float g_off[(size_t)BQ * 256];
__device__ float g_aw [(size_t)BQ * 128];
__device__ float g_tmp[(size_t)BQ * 256];

__device__ __forceinline__ uint32_t f2tf(float x) {
    uint32_t r; asm("cvt.rna.tf32.f32 %0, %1;" : "=r"(r) : "f"(x)); return r;
}

// ---------------------------------------------------------------------------
// TF32 mma.sync GEMM with bias: C[M,N] = A[M,K]*B[K,N] + bias[N]
// BM=128, BN=128, BK=32. 256 threads = 8 warps, warp tile 64x32.
// Double-buffered smem, one __syncthreads per K-tile.
// Smem stride 136: fragment LDS banks (tig*8+gid) -> conflict-free.
// ---------------------------------------------------------------------------
template <int BN>
__global__ __launch_bounds__(256, 2) void gemm_tf32(
    const float* __restrict__ A, const float* __restrict__ B,
    const float* __restrict__ bias, float* __restrict__ C,
    int M, int N, int K)
{
    constexpr int BNS   = BN + 8;             // B smem stride (words)
    constexpr int ASZ   = 32 * 136;           // words per A buffer
    constexpr int BSZ   = 32 * BNS;           // words per B buffer
    constexpr int WCOLS = BN / 32;            // 4 (BN=128)
    constexpr int WROWS = 8 / WCOLS;          // 2
    constexpr int MI    = (128 / WROWS) / 16; // 4
    constexpr int NB4   = BN / 32;            // float4 per thread for B tile

    extern __shared__ uint32_t sm[];          // [2][ASZ+BSZ]

    const int tid  = threadIdx.x;
    const int lane = tid & 31;
    const int w    = tid >> 5;
    const int gid  = lane >> 2;
    const int tig  = lane & 3;
    const int brow = blockIdx.y * 128;
    const int bcol = blockIdx.x * BN;
    const int m0   = (w / WCOLS) * (128 / WROWS);
    const int n0   = (w % WCOLS) * 32;

    float acc[MI][4][4];
    #pragma unroll
    for (int mi = 0; mi < MI; mi++)
        #pragma unroll
        for (int nj = 0; nj < 4; nj++)
            #pragma unroll
            for (int r = 0; r < 4; r++) acc[mi][nj][r] = 0.f;

    float4 pa[4], pb[NB4];

    auto loadG = [&](int k0) {
        #pragma unroll
        for (int i = 0; i < 4; ++i) {
            int c = tid + i * 256, row = c >> 3, slot = c & 7;
            int gr = min(brow + row, M - 1);
            pa[i] = *reinterpret_cast<const float4*>(A + (size_t)gr * K + k0 + slot * 4);
        }
        #pragma unroll
        for (int i = 0; i < NB4; ++i) {
            int c = tid + i * 256, kr = c / (BN / 4), c4 = c % (BN / 4);
            pb[i] = *reinterpret_cast<const float4*>(B + (size_t)(k0 + kr) * N + bcol + c4 * 4);
        }
    };
    auto storeS = [&](int p) {
        uint32_t* As = sm + p * (ASZ + BSZ);
        uint32_t* Bs = As + ASZ;
        #pragma unroll
        for (int i = 0; i < 4; ++i) {
            int c = tid + i * 256, row = c >> 3, slot = c & 7;
            As[(slot * 4 + 0) * 136 + row] = f2tf(pa[i].x);
            As[(slot * 4 + 1) * 136 + row] = f2tf(pa[i].y);
            As[(slot * 4 + 2) * 136 + row] = f2tf(pa[i].z);
            As[(slot * 4 + 3) * 136 + row] = f2tf(pa[i].w);
        }
        #pragma unroll
        for (int i = 0; i < NB4; ++i) {
            int c = tid + i * 256, kr = c / (BN / 4), c4 = c % (BN / 4);
            Bs[kr * BNS + c4 * 4 + 0] = f2tf(pb[i].x);
            Bs[kr * BNS + c4 * 4 + 1] = f2tf(pb[i].y);
            Bs[kr * BNS + c4 * 4 + 2] = f2tf(pb[i].z);
            Bs[kr * BNS + c4 * 4 + 3] = f2tf(pb[i].w);
        }
    };
    auto compute = [&](int p) {
        const uint32_t* As = sm + p * (ASZ + BSZ);
        const uint32_t* Bs = As + ASZ;
        #pragma unroll
        for (int ks = 0; ks < 4; ks++) {
            const int k = ks * 8;
            uint32_t a[MI][4], b[4][2];
            #pragma unroll
            for (int mi = 0; mi < MI; mi++) {
                int mb = m0 + mi * 16 + gid;
                a[mi][0] = As[(k + tig    ) * 136 + mb    ];
                a[mi][1] = As[(k + tig    ) * 136 + mb + 8];
                a[mi][2] = As[(k + tig + 4) * 136 + mb    ];
                a[mi][3] = As[(k + tig + 4) * 136 + mb + 8];
            }
            #pragma unroll
            for (int nj = 0; nj < 4; nj++) {
                int nb = n0 + nj * 8 + gid;
                b[nj][0] = Bs[(k + tig    ) * BNS + nb];
                b[nj][1] = Bs[(k + tig + 4) * BNS + nb];
            }
            #pragma unroll
            for (int mi = 0; mi < MI; mi++)
                #pragma unroll
                for (int nj = 0; nj < 4; nj++) {
                    asm volatile(
                        "mma.sync.aligned.m16n8k8.row.col.f32.tf32.tf32.f32 "
                        "{%0,%1,%2,%3}, {%4,%5,%6,%7}, {%8,%9}, {%0,%1,%2,%3};"
                        : "+f"(acc[mi][nj][0]), "+f"(acc[mi][nj][1]),
                          "+f"(acc[mi][nj][2]), "+f"(acc[mi][nj][3])
                        : "r"(a[mi][0]), "r"(a[mi][1]), "r"(a[mi][2]), "r"(a[mi][3]),
                          "r"(b[nj][0]), "r"(b[nj][1]));
                }
        }
    };

    const int T = K / 32;
    loadG(0);
    storeS(0);
    __syncthreads();
    for (int t = 0; t < T; t++) {
        if (t + 1 < T) loadG((t + 1) * 32);
        compute(t & 1);
        if (t + 1 < T) storeS((t + 1) & 1);
        __syncthreads();
    }

    // Epilogue: c0/c1 -> (row, 2*tig, 2*tig+1); c2/c3 -> row+8
    #pragma unroll
    for (int mi = 0; mi < MI; mi++) {
        #pragma unroll
        for (int nj = 0; nj < 4; nj++) {
            int col = bcol + n0 + nj * 8 + 2 * tig;
            float b0 = bias[col], b1 = bias[col + 1];
            int r0 = brow + m0 + mi * 16 + gid;
            if (r0 < M) {
                float2 v0 = make_float2(acc[mi][nj][0] + b0, acc[mi][nj][1] + b1);
                *reinterpret_cast<float2*>(C + (size_t)r0 * N + col) = v0;
            }
            int r1 = r0 + 8;
            if (r1 < M) {
                float2 v1 = make_float2(acc[mi][nj][2] + b0, acc[mi][nj][3] + b1);
                *reinterpret_cast<float2*>(C + (size_t)r1 * N + col) = v1;
            }
        }
    }
}

// ---------------------------------------------------------------------------
// Fused softmax + sampling. One block per (b,q), 256 threads.
// Stage 2 batches 4 samples (16 outstanding LDGs) into 4 accumulators.
// ---------------------------------------------------------------------------
__global__ __launch_bounds__(256, 4) void msda_sample(
    const float* __restrict__ ref, const float* __restrict__ offp,
    const float* __restrict__ awp, const int* __restrict__ shapes,
    const int* __restrict__ starts, const float* __restrict__ v,
    float* __restrict__ tmp)
{
    const int bq  = blockIdx.x;
    const int b   = bq / Qn;
    const int tid = threadIdx.x;

    __shared__ int4   sIdx[128];
    __shared__ float4 sW[128];

    if (tid < 128) {
        const int l = (tid >> 2) & 3;
        const int Hl = shapes[2 * l], Wl = shapes[2 * l + 1];
        const int st = starts[l];

        float logit = awp[(size_t)bq * 128 + tid];
        float m = logit;
        #pragma unroll
        for (int d = 8; d >= 1; d >>= 1)
            m = fmaxf(m, __shfl_xor_sync(0xffffffffu, m, d));
        float e = __expf(logit - m);
        float s = e;
        #pragma unroll
        for (int d = 8; d >= 1; d >>= 1)
            s += __shfl_xor_sync(0xffffffffu, s, d);
        const float wgt = e / s;

        const float2 off = reinterpret_cast<const float2*>(offp)[(size_t)bq * 128 + tid];
        const float rx = ref[(size_t)bq * (LEVELS * 2) + 2 * l];
        const float ry = ref[(size_t)bq * (LEVELS * 2) + 2 * l + 1];
        const float x = rx * (float)Wl + off.x - 0.5f;
        const float y = ry * (float)Hl + off.y - 0.5f;

        const float x0f = floorf(x), y0f = floorf(y);
        const int x0 = (int)x0f, y0 = (int)y0f;
        const float fx = x - x0f, fy = y - y0f;
        const int x1 = x0 + 1, y1 = y0 + 1;
        const bool bx0 = (x0 >= 0) & (x0 < Wl);
        const bool bx1 = (x1 >= 0) & (x1 < Wl);
        const bool by0 = (y0 >= 0) & (y0 < Hl);
        const bool by1 = (y1 >= 0) & (y1 < Hl);
        const int cx0 = min(max(x0, 0), Wl - 1), cx1 = min(max(x1, 0), Wl - 1);
        const int cy0 = min(max(y0, 0), Hl - 1), cy1 = min(max(y1, 0), Hl - 1);

        sIdx[tid] = make_int4(st + cy0 * Wl + cx0, st + cy0 * Wl + cx1,
                              st + cy1 * Wl + cx0, st + cy1 * Wl + cx1);
        sW[tid] = make_float4(
            (bx0 && by0) ? (1.f - fx) * (1.f - fy) * wgt : 0.f,
            (bx1 && by0) ? fx * (1.f - fy) * wgt : 0.f,
            (bx0 && by1) ? (1.f - fx) * fy * wgt : 0.f,
            (bx1 && by1) ? fx * fy * wgt : 0.f);
    }
    __syncthreads();

    const int h    = tid >> 5;
    const int lane = tid & 31;
    const float* vb = v + (size_t)b * NUM_KEYS * EMBED + h * HEAD_DIM + lane;

    float acc[4] = {0.f, 0.f, 0.f, 0.f};
    #pragma unroll
    for (int i = 0; i < 16; i += 4) {
        int4   id[4];
        float4 wv[4];
        #pragma unroll
        for (int j = 0; j < 4; j++) {
            id[j] = sIdx[h * 16 + i + j];
            wv[j] = sW[h * 16 + i + j];
        }
        float g[4][4];
        #pragma unroll
        for (int j = 0; j < 4; j++) {
            g[j][0] = vb[(size_t)id[j].x * EMBED];
            g[j][1] = vb[(size_t)id[j].y * EMBED];
            g[j][2] = vb[(size_t)id[j].z * EMBED];
            g[j][3] = vb[(size_t)id[j].w * EMBED];
        }
        #pragma unroll
        for (int j = 0; j < 4; j++) {
            acc[j] = fmaf(wv[j].x, g[j][0], acc[j]);
            acc[j] = fmaf(wv[j].y, g[j][1], acc[j]);
            acc[j] = fmaf(wv[j].z, g[j][2], acc[j]);
            acc[j] = fmaf(wv[j].w, g[j][3], acc[j]);
        }
    }
    tmp[(size_t)bq * 256 + tid] = (acc[0] + acc[1]) + (acc[2] + acc[3]);
}

// ---------------------------------------------------------------------------
extern "C" void kernel_launch(void* const* d_in, const int* in_sizes, int n_in,
                              void* d_out, int out_size)
{
    const float* query  = (const float*)d_in[0];
    const float* refpts = (const float*)d_in[1];
    const float* value  = (const float*)d_in[2];
    const int*   shapes = (const int*)  d_in[3];
    const int*   starts = (const int*)  d_in[4];
    const float* W_off  = (const float*)d_in[5];
    const float* b_off  = (const float*)d_in[6];
    const float* W_attn = (const float*)d_in[7];
    const float* b_attn = (const float*)d_in[8];
    const float* W_val  = (const float*)d_in[9];
    const float* b_val  = (const float*)d_in[10];
    const float* W_out  = (const float*)d_in[11];
    const float* b_out  = (const float*)d_in[12];
    float* out = (float*)d_out;

    float *pv, *poff, *paw, *ptmp;
    cudaGetSymbolAddress((void**)&pv,   g_v);
    cudaGetSymbolAddress((void**)&poff, g_off);
    cudaGetSymbolAddress((void**)&paw,  g_aw);
    cudaGetSymbolAddress((void**)&ptmp, g_tmp);

    const int SM128 = 2 * (32 * 136 + 32 * 136) * 4;   // 69632 B
    cudaFuncSetAttribute(gemm_tf32<128>, cudaFuncAttributeMaxDynamicSharedMemorySize, SM128);

    // 1) value projection: [106352,256] @ [256,256]
    {
        dim3 grid(2, (MV + 127) / 128);
        gemm_tf32<128><<<grid, 256, SM128>>>(value, W_val, b_val, pv, MV, 256, 256);
    }
    // 2a) offset projection: [7200,256] @ [256,256]
    {
        dim3 grid(2, (BQ + 127) / 128);
        gemm_tf32<128><<<grid, 256, SM128>>>(query, W_off, b_off, poff, BQ, 256, 256);
    }
    // 2b) attn projection: [7200,256] @ [256,128]
    {
        dim3 grid(1, (BQ + 127) / 128);
        gemm_tf32<128><<<grid, 256, SM128>>>(query, W_attn, b_attn, paw, BQ, 128, 256);
    }
    // 3) fused softmax + sampling
    msda_sample<<<BQ, 256>>>(refpts, poff, paw, shapes, starts, pv, ptmp);
    // 4) output projection: [7200,256] @ [256,256]
    {
        dim3 grid(2, (BQ + 127) / 128);
        gemm_tf32<128><<<grid, 256, SM128>>>(ptmp, W_out, b_out, out, BQ, 256, 256);
    }
}

// round 6
// speedup vs baseline: 3.5060x; 1.5537x over previous
#include <cuda_runtime.h>
#include <cuda_fp16.h>
#include <cstdint>

// Problem constants
#define Bn 8
#define Qn 900
#define EMBED 256
#define HEADS 8
#define LEVELS 4
#define POINTS 4
#define HEAD_DIM 32
#define NUM_KEYS 13294
#define BQ (Bn*Qn)            // 7200
#define MV (Bn*NUM_KEYS)      // 106352

// Scratch (device globals; no runtime allocation)
__device__ float g_v  [(size_t)MV * EMBED];
__device__ float g_off[(size_t)BQ * 256];
__device__ float g_aw [(size_t)BQ * 128];
__device__ float g_tmp[(size_t)BQ * 256];

__device__ __forceinline__ uint32_t packh2(float a, float b) {
    __half2 h = __floats2half2_rn(a, b);
    return *reinterpret_cast<uint32_t*>(&h);
}

// ---------------------------------------------------------------------------
// FP16 mma.sync GEMM with bias (fp32 in/out/accum): C[M,N] = A*B + bias
// BM=128, BN=128, BK=32. 256 threads = 8 warps, warp tile 64x32.
// m16n8k16: k-pairs packed in 32-bit words -> same fragment indexing as the
// validated tf32 kernel. A smem [m][k2] stride 20 (banks 20*gid+tig bijective),
// B smem [k2][n] stride 136 (banks 8*tig+gid bijective). Double-buffered.
// ---------------------------------------------------------------------------
template <int BN>
__global__ __launch_bounds__(256, 2) void gemm_f16(
    const float* __restrict__ A, const float* __restrict__ B,
    const float* __restrict__ bias, float* __restrict__ C,
    int M, int N, int K)
{
    constexpr int AST = 20;             // A smem stride (words), k2 dim 16 + pad
    constexpr int BST = BN + 8;         // 136
    constexpr int ASZ = 128 * AST;      // 2560 words
    constexpr int BSZ = 16 * BST;       // 2176 words
    constexpr int WCOLS = BN / 32;      // 4
    constexpr int WROWS = 8 / WCOLS;    // 2
    constexpr int MI = (128 / WROWS) / 16;  // 4

    extern __shared__ uint32_t sm[];    // [2][ASZ+BSZ]

    const int tid  = threadIdx.x;
    const int lane = tid & 31;
    const int w    = tid >> 5;
    const int gid  = lane >> 2;
    const int tig  = lane & 3;
    const int brow = blockIdx.y * 128;
    const int bcol = blockIdx.x * BN;
    const int m0   = (w / WCOLS) * (128 / WROWS);
    const int n0   = (w % WCOLS) * 32;

    float acc[MI][4][4];
    #pragma unroll
    for (int mi = 0; mi < MI; mi++)
        #pragma unroll
        for (int nj = 0; nj < 4; nj++)
            #pragma unroll
            for (int r = 0; r < 4; r++) acc[mi][nj][r] = 0.f;

    float4 pa[4], pbl[2], pbh[2];

    auto loadG = [&](int k0) {
        #pragma unroll
        for (int i = 0; i < 4; ++i) {
            int c = tid + i * 256, row = c >> 3, slot = c & 7;
            int gr = min(brow + row, M - 1);
            pa[i] = *reinterpret_cast<const float4*>(A + (size_t)gr * K + k0 + slot * 4);
        }
        #pragma unroll
        for (int i = 0; i < 2; ++i) {
            int g = tid + i * 256, k2 = g >> 5, c4 = g & 31;
            pbl[i] = *reinterpret_cast<const float4*>(B + (size_t)(k0 + 2 * k2    ) * N + bcol + c4 * 4);
            pbh[i] = *reinterpret_cast<const float4*>(B + (size_t)(k0 + 2 * k2 + 1) * N + bcol + c4 * 4);
        }
    };
    auto storeS = [&](int p) {
        uint32_t* As = sm + p * (ASZ + BSZ);
        uint32_t* Bs = As + ASZ;
        #pragma unroll
        for (int i = 0; i < 4; ++i) {
            int c = tid + i * 256, row = c >> 3, slot = c & 7;
            uint2 t = { packh2(pa[i].x, pa[i].y), packh2(pa[i].z, pa[i].w) };
            *reinterpret_cast<uint2*>(&As[row * AST + 2 * slot]) = t;
        }
        #pragma unroll
        for (int i = 0; i < 2; ++i) {
            int g = tid + i * 256, k2 = g >> 5, c4 = g & 31;
            uint4 t = { packh2(pbl[i].x, pbh[i].x), packh2(pbl[i].y, pbh[i].y),
                        packh2(pbl[i].z, pbh[i].z), packh2(pbl[i].w, pbh[i].w) };
            *reinterpret_cast<uint4*>(&Bs[k2 * BST + c4 * 4]) = t;
        }
    };
    auto compute = [&](int p) {
        const uint32_t* As = sm + p * (ASZ + BSZ);
        const uint32_t* Bs = As + ASZ;
        #pragma unroll
        for (int ks = 0; ks < 2; ks++) {
            const int k2 = ks * 8;
            uint32_t a[MI][4], b[4][2];
            #pragma unroll
            for (int mi = 0; mi < MI; mi++) {
                int mb = m0 + mi * 16 + gid;
                a[mi][0] = As[(mb    ) * AST + k2 + tig    ];
                a[mi][1] = As[(mb + 8) * AST + k2 + tig    ];
                a[mi][2] = As[(mb    ) * AST + k2 + tig + 4];
                a[mi][3] = As[(mb + 8) * AST + k2 + tig + 4];
            }
            #pragma unroll
            for (int nj = 0; nj < 4; nj++) {
                int nb = n0 + nj * 8 + gid;
                b[nj][0] = Bs[(k2 + tig    ) * BST + nb];
                b[nj][1] = Bs[(k2 + tig + 4) * BST + nb];
            }
            #pragma unroll
            for (int mi = 0; mi < MI; mi++)
                #pragma unroll
                for (int nj = 0; nj < 4; nj++) {
                    asm volatile(
                        "mma.sync.aligned.m16n8k16.row.col.f32.f16.f16.f32 "
                        "{%0,%1,%2,%3}, {%4,%5,%6,%7}, {%8,%9}, {%0,%1,%2,%3};"
                        : "+f"(acc[mi][nj][0]), "+f"(acc[mi][nj][1]),
                          "+f"(acc[mi][nj][2]), "+f"(acc[mi][nj][3])
                        : "r"(a[mi][0]), "r"(a[mi][1]), "r"(a[mi][2]), "r"(a[mi][3]),
                          "r"(b[nj][0]), "r"(b[nj][1]));
                }
        }
    };

    const int T = K / 32;
    loadG(0);
    storeS(0);
    __syncthreads();
    for (int t = 0; t < T; t++) {
        if (t + 1 < T) loadG((t + 1) * 32);
        compute(t & 1);
        if (t + 1 < T) storeS((t + 1) & 1);
        __syncthreads();
    }

    // Epilogue: c0/c1 -> (row, 2*tig, 2*tig+1); c2/c3 -> row+8
    #pragma unroll
    for (int mi = 0; mi < MI; mi++) {
        #pragma unroll
        for (int nj = 0; nj < 4; nj++) {
            int col = bcol + n0 + nj * 8 + 2 * tig;
            float b0 = bias[col], b1 = bias[col + 1];
            int r0 = brow + m0 + mi * 16 + gid;
            if (r0 < M) {
                float2 v0 = make_float2(acc[mi][nj][0] + b0, acc[mi][nj][1] + b1);
                *reinterpret_cast<float2*>(C + (size_t)r0 * N + col) = v0;
            }
            int r1 = r0 + 8;
            if (r1 < M) {
                float2 v1 = make_float2(acc[mi][nj][2] + b0, acc[mi][nj][3] + b1);
                *reinterpret_cast<float2*>(C + (size_t)r1 * N + col) = v1;
            }
        }
    }
}

// ---------------------------------------------------------------------------
// Fused softmax + sampling (round-2 version: 40 regs, best measured).
// ---------------------------------------------------------------------------
__global__ __launch_bounds__(256) void msda_sample(
    const float* __restrict__ ref, const float* __restrict__ offp,
    const float* __restrict__ awp, const int* __restrict__ shapes,
    const int* __restrict__ starts, const float* __restrict__ v,
    float* __restrict__ tmp)
{
    const int bq  = blockIdx.x;
    const int b   = bq / Qn;
    const int tid = threadIdx.x;

    __shared__ int4   sIdx[128];
    __shared__ float4 sW[128];

    if (tid < 128) {
        const int l = (tid >> 2) & 3;
        const int Hl = shapes[2 * l], Wl = shapes[2 * l + 1];
        const int st = starts[l];

        float logit = awp[(size_t)bq * 128 + tid];
        float m = logit;
        #pragma unroll
        for (int d = 8; d >= 1; d >>= 1)
            m = fmaxf(m, __shfl_xor_sync(0xffffffffu, m, d));
        float e = __expf(logit - m);
        float s = e;
        #pragma unroll
        for (int d = 8; d >= 1; d >>= 1)
            s += __shfl_xor_sync(0xffffffffu, s, d);
        const float wgt = e / s;

        const float2 off = reinterpret_cast<const float2*>(offp)[(size_t)bq * 128 + tid];
        const float rx = ref[(size_t)bq * (LEVELS * 2) + 2 * l];
        const float ry = ref[(size_t)bq * (LEVELS * 2) + 2 * l + 1];
        const float x = rx * (float)Wl + off.x - 0.5f;
        const float y = ry * (float)Hl + off.y - 0.5f;

        const float x0f = floorf(x), y0f = floorf(y);
        const int x0 = (int)x0f, y0 = (int)y0f;
        const float fx = x - x0f, fy = y - y0f;
        const int x1 = x0 + 1, y1 = y0 + 1;
        const bool bx0 = (x0 >= 0) & (x0 < Wl);
        const bool bx1 = (x1 >= 0) & (x1 < Wl);
        const bool by0 = (y0 >= 0) & (y0 < Hl);
        const bool by1 = (y1 >= 0) & (y1 < Hl);
        const int cx0 = min(max(x0, 0), Wl - 1), cx1 = min(max(x1, 0), Wl - 1);
        const int cy0 = min(max(y0, 0), Hl - 1), cy1 = min(max(y1, 0), Hl - 1);

        sIdx[tid] = make_int4(st + cy0 * Wl + cx0, st + cy0 * Wl + cx1,
                              st + cy1 * Wl + cx0, st + cy1 * Wl + cx1);
        sW[tid] = make_float4(
            (bx0 && by0) ? (1.f - fx) * (1.f - fy) * wgt : 0.f,
            (bx1 && by0) ? fx * (1.f - fy) * wgt : 0.f,
            (bx0 && by1) ? (1.f - fx) * fy * wgt : 0.f,
            (bx1 && by1) ? fx * fy * wgt : 0.f);
    }
    __syncthreads();

    const int h    = tid >> 5;
    const int lane = tid & 31;
    const float* vb = v + (size_t)b * NUM_KEYS * EMBED + h * HEAD_DIM + lane;

    float acc = 0.f;
    #pragma unroll
    for (int i = 0; i < 16; i++) {
        const int4   id = sIdx[h * 16 + i];
        const float4 wv = sW[h * 16 + i];
        acc = fmaf(wv.x, vb[(size_t)id.x * EMBED], acc);
        acc = fmaf(wv.y, vb[(size_t)id.y * EMBED], acc);
        acc = fmaf(wv.z, vb[(size_t)id.z * EMBED], acc);
        acc = fmaf(wv.w, vb[(size_t)id.w * EMBED], acc);
    }
    tmp[(size_t)bq * 256 + tid] = acc;
}

// ---------------------------------------------------------------------------
extern "C" void kernel_launch(void* const* d_in, const int* in_sizes, int n_in,
                              void* d_out, int out_size)
{
    const float* query  = (const float*)d_in[0];
    const float* refpts = (const float*)d_in[1];
    const float* value  = (const float*)d_in[2];
    const int*   shapes = (const int*)  d_in[3];
    const int*   starts = (const int*)  d_in[4];
    const float* W_off  = (const float*)d_in[5];
    const float* b_off  = (const float*)d_in[6];
    const float* W_attn = (const float*)d_in[7];
    const float* b_attn = (const float*)d_in[8];
    const float* W_val  = (const float*)d_in[9];
    const float* b_val  = (const float*)d_in[10];
    const float* W_out  = (const float*)d_in[11];
    const float* b_out  = (const float*)d_in[12];
    float* out = (float*)d_out;

    float *pv, *poff, *paw, *ptmp;
    cudaGetSymbolAddress((void**)&pv,   g_v);
    cudaGetSymbolAddress((void**)&poff, g_off);
    cudaGetSymbolAddress((void**)&paw,  g_aw);
    cudaGetSymbolAddress((void**)&ptmp, g_tmp);

    const int SMEM = 2 * (128 * 20 + 16 * 136) * 4;   // 37888 B
    cudaFuncSetAttribute(gemm_f16<128>, cudaFuncAttributeMaxDynamicSharedMemorySize, SMEM);

    // 1) value projection: [106352,256] @ [256,256]
    {
        dim3 grid(2, (MV + 127) / 128);
        gemm_f16<128><<<grid, 256, SMEM>>>(value, W_val, b_val, pv, MV, 256, 256);
    }
    // 2a) offset projection: [7200,256] @ [256,256]
    {
        dim3 grid(2, (BQ + 127) / 128);
        gemm_f16<128><<<grid, 256, SMEM>>>(query, W_off, b_off, poff, BQ, 256, 256);
    }
    // 2b) attn projection: [7200,256] @ [256,128]
    {
        dim3 grid(1, (BQ + 127) / 128);
        gemm_f16<128><<<grid, 256, SMEM>>>(query, W_attn, b_attn, paw, BQ, 128, 256);
    }
    // 3) fused softmax + sampling
    msda_sample<<<BQ, 256>>>(refpts, poff, paw, shapes, starts, pv, ptmp);
    // 4) output projection: [7200,256] @ [256,256]
    {
        dim3 grid(2, (BQ + 127) / 128);
        gemm_f16<128><<<grid, 256, SMEM>>>(ptmp, W_out, b_out, out, BQ, 256, 256);
    }
}

// round 7
// speedup vs baseline: 3.8532x; 1.0990x over previous
#include <cuda_runtime.h>
#include <cuda_fp16.h>
#include <cstdint>

// Problem constants
#define Bn 8
#define Qn 900
#define EMBED 256
#define HEADS 8
#define LEVELS 4
#define POINTS 4
#define HEAD_DIM 32
#define NUM_KEYS 13294
#define BQ (Bn*Qn)            // 7200
#define MV (Bn*NUM_KEYS)      // 106352

// Scratch (device globals; no runtime allocation)
__device__ __half g_vh [(size_t)MV * EMBED];  // projected value, fp16
__device__ float  g_off[(size_t)BQ * 256];
__device__ float  g_aw [(size_t)BQ * 128];
__device__ float  g_tmp[(size_t)BQ * 256];

__device__ __forceinline__ uint32_t packh2(float a, float b) {
    __half2 h = __floats2half2_rn(a, b);
    return *reinterpret_cast<uint32_t*>(&h);
}

// ---------------------------------------------------------------------------
// FP16 mma.sync GEMM with bias (fp32 in, fp32 accum, fp32 or fp16 out).
// BM=128, BN=128, BK=32. 256 threads = 8 warps, warp tile 64x32.
// m16n8k16 with k-pairs packed per 32-bit word; conflict-free smem
// (A [m][k2] stride 20, B [k2][n] stride 136). Double-buffered.
// ---------------------------------------------------------------------------
template <int BN, bool HOUT>
__global__ __launch_bounds__(256, 2) void gemm_f16(
    const float* __restrict__ A, const float* __restrict__ B,
    const float* __restrict__ bias, void* __restrict__ Cv,
    int M, int N, int K)
{
    constexpr int AST = 20;
    constexpr int BST = BN + 8;
    constexpr int ASZ = 128 * AST;
    constexpr int BSZ = 16 * BST;
    constexpr int WCOLS = BN / 32;
    constexpr int WROWS = 8 / WCOLS;
    constexpr int MI = (128 / WROWS) / 16;

    extern __shared__ uint32_t sm[];

    const int tid  = threadIdx.x;
    const int lane = tid & 31;
    const int w    = tid >> 5;
    const int gid  = lane >> 2;
    const int tig  = lane & 3;
    const int brow = blockIdx.y * 128;
    const int bcol = blockIdx.x * BN;
    const int m0   = (w / WCOLS) * (128 / WROWS);
    const int n0   = (w % WCOLS) * 32;

    float acc[MI][4][4];
    #pragma unroll
    for (int mi = 0; mi < MI; mi++)
        #pragma unroll
        for (int nj = 0; nj < 4; nj++)
            #pragma unroll
            for (int r = 0; r < 4; r++) acc[mi][nj][r] = 0.f;

    float4 pa[4], pbl[2], pbh[2];

    auto loadG = [&](int k0) {
        #pragma unroll
        for (int i = 0; i < 4; ++i) {
            int c = tid + i * 256, row = c >> 3, slot = c & 7;
            int gr = min(brow + row, M - 1);
            pa[i] = *reinterpret_cast<const float4*>(A + (size_t)gr * K + k0 + slot * 4);
        }
        #pragma unroll
        for (int i = 0; i < 2; ++i) {
            int g = tid + i * 256, k2 = g >> 5, c4 = g & 31;
            pbl[i] = *reinterpret_cast<const float4*>(B + (size_t)(k0 + 2 * k2    ) * N + bcol + c4 * 4);
            pbh[i] = *reinterpret_cast<const float4*>(B + (size_t)(k0 + 2 * k2 + 1) * N + bcol + c4 * 4);
        }
    };
    auto storeS = [&](int p) {
        uint32_t* As = sm + p * (ASZ + BSZ);
        uint32_t* Bs = As + ASZ;
        #pragma unroll
        for (int i = 0; i < 4; ++i) {
            int c = tid + i * 256, row = c >> 3, slot = c & 7;
            uint2 t = { packh2(pa[i].x, pa[i].y), packh2(pa[i].z, pa[i].w) };
            *reinterpret_cast<uint2*>(&As[row * AST + 2 * slot]) = t;
        }
        #pragma unroll
        for (int i = 0; i < 2; ++i) {
            int g = tid + i * 256, k2 = g >> 5, c4 = g & 31;
            uint4 t = { packh2(pbl[i].x, pbh[i].x), packh2(pbl[i].y, pbh[i].y),
                        packh2(pbl[i].z, pbh[i].z), packh2(pbl[i].w, pbh[i].w) };
            *reinterpret_cast<uint4*>(&Bs[k2 * BST + c4 * 4]) = t;
        }
    };
    auto compute = [&](int p) {
        const uint32_t* As = sm + p * (ASZ + BSZ);
        const uint32_t* Bs = As + ASZ;
        #pragma unroll
        for (int ks = 0; ks < 2; ks++) {
            const int k2 = ks * 8;
            uint32_t a[MI][4], b[4][2];
            #pragma unroll
            for (int mi = 0; mi < MI; mi++) {
                int mb = m0 + mi * 16 + gid;
                a[mi][0] = As[(mb    ) * AST + k2 + tig    ];
                a[mi][1] = As[(mb + 8) * AST + k2 + tig    ];
                a[mi][2] = As[(mb    ) * AST + k2 + tig + 4];
                a[mi][3] = As[(mb + 8) * AST + k2 + tig + 4];
            }
            #pragma unroll
            for (int nj = 0; nj < 4; nj++) {
                int nb = n0 + nj * 8 + gid;
                b[nj][0] = Bs[(k2 + tig    ) * BST + nb];
                b[nj][1] = Bs[(k2 + tig + 4) * BST + nb];
            }
            #pragma unroll
            for (int mi = 0; mi < MI; mi++)
                #pragma unroll
                for (int nj = 0; nj < 4; nj++) {
                    asm volatile(
                        "mma.sync.aligned.m16n8k16.row.col.f32.f16.f16.f32 "
                        "{%0,%1,%2,%3}, {%4,%5,%6,%7}, {%8,%9}, {%0,%1,%2,%3};"
                        : "+f"(acc[mi][nj][0]), "+f"(acc[mi][nj][1]),
                          "+f"(acc[mi][nj][2]), "+f"(acc[mi][nj][3])
                        : "r"(a[mi][0]), "r"(a[mi][1]), "r"(a[mi][2]), "r"(a[mi][3]),
                          "r"(b[nj][0]), "r"(b[nj][1]));
                }
        }
    };

    const int T = K / 32;
    loadG(0);
    storeS(0);
    __syncthreads();
    for (int t = 0; t < T; t++) {
        if (t + 1 < T) loadG((t + 1) * 32);
        compute(t & 1);
        if (t + 1 < T) storeS((t + 1) & 1);
        __syncthreads();
    }

    // Epilogue
    #pragma unroll
    for (int mi = 0; mi < MI; mi++) {
        #pragma unroll
        for (int nj = 0; nj < 4; nj++) {
            int col = bcol + n0 + nj * 8 + 2 * tig;
            float b0 = bias[col], b1 = bias[col + 1];
            int r0 = brow + m0 + mi * 16 + gid;
            int r1 = r0 + 8;
            if (HOUT) {
                __half* C = (__half*)Cv;
                if (r0 < M)
                    *reinterpret_cast<uint32_t*>(C + (size_t)r0 * N + col) =
                        packh2(acc[mi][nj][0] + b0, acc[mi][nj][1] + b1);
                if (r1 < M)
                    *reinterpret_cast<uint32_t*>(C + (size_t)r1 * N + col) =
                        packh2(acc[mi][nj][2] + b0, acc[mi][nj][3] + b1);
            } else {
                float* C = (float*)Cv;
                if (r0 < M) {
                    float2 v0 = make_float2(acc[mi][nj][0] + b0, acc[mi][nj][1] + b1);
                    *reinterpret_cast<float2*>(C + (size_t)r0 * N + col) = v0;
                }
                if (r1 < M) {
                    float2 v1 = make_float2(acc[mi][nj][2] + b0, acc[mi][nj][3] + b1);
                    *reinterpret_cast<float2*>(C + (size_t)r1 * N + col) = v1;
                }
            }
        }
    }
}

// ---------------------------------------------------------------------------
// Fused softmax + sampling over fp16 value. One block per (b,q), 256 threads.
// Warp = head. Lane = 16*sgrp + c16: sgrp in {0,1} splits the 16 samples,
// c16 owns a channel PAIR (one __half2 gather per corner -> 64B/warp line).
// Final xor-16 shuffle reduces the two sample-halves.
// ---------------------------------------------------------------------------
__global__ __launch_bounds__(256) void msda_sample(
    const float* __restrict__ ref, const float* __restrict__ offp,
    const float* __restrict__ awp, const int* __restrict__ shapes,
    const int* __restrict__ starts, const __half* __restrict__ v,
    float* __restrict__ tmp)
{
    const int bq  = blockIdx.x;
    const int b   = bq / Qn;
    const int tid = threadIdx.x;

    __shared__ int4   sIdx[128];
    __shared__ float4 sW[128];

    if (tid < 128) {
        const int l = (tid >> 2) & 3;
        const int Hl = shapes[2 * l], Wl = shapes[2 * l + 1];
        const int st = starts[l];

        float logit = awp[(size_t)bq * 128 + tid];
        float m = logit;
        #pragma unroll
        for (int d = 8; d >= 1; d >>= 1)
            m = fmaxf(m, __shfl_xor_sync(0xffffffffu, m, d));
        float e = __expf(logit - m);
        float s = e;
        #pragma unroll
        for (int d = 8; d >= 1; d >>= 1)
            s += __shfl_xor_sync(0xffffffffu, s, d);
        const float wgt = e / s;

        const float2 off = reinterpret_cast<const float2*>(offp)[(size_t)bq * 128 + tid];
        const float rx = ref[(size_t)bq * (LEVELS * 2) + 2 * l];
        const float ry = ref[(size_t)bq * (LEVELS * 2) + 2 * l + 1];
        const float x = rx * (float)Wl + off.x - 0.5f;
        const float y = ry * (float)Hl + off.y - 0.5f;

        const float x0f = floorf(x), y0f = floorf(y);
        const int x0 = (int)x0f, y0 = (int)y0f;
        const float fx = x - x0f, fy = y - y0f;
        const int x1 = x0 + 1, y1 = y0 + 1;
        const bool bx0 = (x0 >= 0) & (x0 < Wl);
        const bool bx1 = (x1 >= 0) & (x1 < Wl);
        const bool by0 = (y0 >= 0) & (y0 < Hl);
        const bool by1 = (y1 >= 0) & (y1 < Hl);
        const int cx0 = min(max(x0, 0), Wl - 1), cx1 = min(max(x1, 0), Wl - 1);
        const int cy0 = min(max(y0, 0), Hl - 1), cy1 = min(max(y1, 0), Hl - 1);

        sIdx[tid] = make_int4(st + cy0 * Wl + cx0, st + cy0 * Wl + cx1,
                              st + cy1 * Wl + cx0, st + cy1 * Wl + cx1);
        sW[tid] = make_float4(
            (bx0 && by0) ? (1.f - fx) * (1.f - fy) * wgt : 0.f,
            (bx1 && by0) ? fx * (1.f - fy) * wgt : 0.f,
            (bx0 && by1) ? (1.f - fx) * fy * wgt : 0.f,
            (bx1 && by1) ? fx * fy * wgt : 0.f);
    }
    __syncthreads();

    const int h    = tid >> 5;
    const int lane = tid & 31;
    const int sgrp = lane >> 4;          // which 8 samples
    const int c16  = lane & 15;          // channel pair
    const __half* vb = v + (size_t)b * NUM_KEYS * EMBED + h * HEAD_DIM + 2 * c16;

    float ax = 0.f, ay = 0.f;
    #pragma unroll
    for (int j = 0; j < 8; j++) {
        const int s = h * 16 + sgrp * 8 + j;
        const int4   id = sIdx[s];
        const float4 wv = sW[s];
        float2 g0 = __half22float2(*reinterpret_cast<const __half2*>(vb + (size_t)id.x * EMBED));
        float2 g1 = __half22float2(*reinterpret_cast<const __half2*>(vb + (size_t)id.y * EMBED));
        float2 g2 = __half22float2(*reinterpret_cast<const __half2*>(vb + (size_t)id.z * EMBED));
        float2 g3 = __half22float2(*reinterpret_cast<const __half2*>(vb + (size_t)id.w * EMBED));
        ax = fmaf(wv.x, g0.x, ax); ay = fmaf(wv.x, g0.y, ay);
        ax = fmaf(wv.y, g1.x, ax); ay = fmaf(wv.y, g1.y, ay);
        ax = fmaf(wv.z, g2.x, ax); ay = fmaf(wv.z, g2.y, ay);
        ax = fmaf(wv.w, g3.x, ax); ay = fmaf(wv.w, g3.y, ay);
    }
    ax += __shfl_xor_sync(0xffffffffu, ax, 16);
    ay += __shfl_xor_sync(0xffffffffu, ay, 16);

    if (sgrp == 0) {
        float2 o = make_float2(ax, ay);
        *reinterpret_cast<float2*>(tmp + (size_t)bq * 256 + h * HEAD_DIM + 2 * c16) = o;
    }
}

// ---------------------------------------------------------------------------
extern "C" void kernel_launch(void* const* d_in, const int* in_sizes, int n_in,
                              void* d_out, int out_size)
{
    const float* query  = (const float*)d_in[0];
    const float* refpts = (const float*)d_in[1];
    const float* value  = (const float*)d_in[2];
    const int*   shapes = (const int*)  d_in[3];
    const int*   starts = (const int*)  d_in[4];
    const float* W_off  = (const float*)d_in[5];
    const float* b_off  = (const float*)d_in[6];
    const float* W_attn = (const float*)d_in[7];
    const float* b_attn = (const float*)d_in[8];
    const float* W_val  = (const float*)d_in[9];
    const float* b_val  = (const float*)d_in[10];
    const float* W_out  = (const float*)d_in[11];
    const float* b_out  = (const float*)d_in[12];
    float* out = (float*)d_out;

    __half* pvh;
    float *poff, *paw, *ptmp;
    cudaGetSymbolAddress((void**)&pvh,  g_vh);
    cudaGetSymbolAddress((void**)&poff, g_off);
    cudaGetSymbolAddress((void**)&paw,  g_aw);
    cudaGetSymbolAddress((void**)&ptmp, g_tmp);

    const int SMEM = 2 * (128 * 20 + 16 * 136) * 4;   // 37888 B
    cudaFuncSetAttribute(gemm_f16<128, true>,  cudaFuncAttributeMaxDynamicSharedMemorySize, SMEM);
    cudaFuncSetAttribute(gemm_f16<128, false>, cudaFuncAttributeMaxDynamicSharedMemorySize, SMEM);

    // 1) value projection -> fp16: [106352,256] @ [256,256]
    {
        dim3 grid(2, (MV + 127) / 128);
        gemm_f16<128, true><<<grid, 256, SMEM>>>(value, W_val, b_val, pvh, MV, 256, 256);
    }
    // 2a) offset projection: [7200,256] @ [256,256]
    {
        dim3 grid(2, (BQ + 127) / 128);
        gemm_f16<128, false><<<grid, 256, SMEM>>>(query, W_off, b_off, poff, BQ, 256, 256);
    }
    // 2b) attn projection: [7200,256] @ [256,128]
    {
        dim3 grid(1, (BQ + 127) / 128);
        gemm_f16<128, false><<<grid, 256, SMEM>>>(query, W_attn, b_attn, paw, BQ, 128, 256);
    }
    // 3) fused softmax + sampling (fp16 gathers)
    msda_sample<<<BQ, 256>>>(refpts, poff, paw, shapes, starts, pvh, ptmp);
    // 4) output projection: [7200,256] @ [256,256]
    {
        dim3 grid(2, (BQ + 127) / 128);
        gemm_f16<128, false><<<grid, 256, SMEM>>>(ptmp, W_out, b_out, out, BQ, 256, 256);
    }
}